// round 16
// baseline (speedup 1.0000x reference)
#include <cuda_runtime.h>
#include <cstdint>

// CRPS loss — sort-network term2 (Batcher 16-sort + order-statistic identity).
//   term1 = mean_i |s_i - y|
//   term2 = sum_{i<j}|s_i - s_j| / 256 = sum_k (2k-15) * s_(k) / 256   (sorted)
//   out   = mean_pixels (term1 - term2)
//
// samples: [16, 4, 1, 256, 256] f32 -> 16 planes of 262144 floats
// target:  [4, 1, 256, 256]     f32 -> 262144 floats
//
// 512 CTAs x 256 threads (best-timed shape), one float2 group (2 pixels) per
// thread. Per pixel: 63 compare-exchanges (FMNMX, alu pipe) + 16-term weighted
// sum + 16-term term1 => 174 ops/pixel vs 272 direct, split across both pipes.

#define NS      16
#define NPIX    (4 * 1 * 256 * 256)     // 262144
#define THREADS 256
#define BLOCKS  (NPIX / 2 / THREADS)    // 512

__device__ float        g_partial[BLOCKS];
__device__ unsigned int g_done = 0;

__device__ __forceinline__ void ce(float& a, float& b) {
    float lo = fminf(a, b);
    b = fmaxf(a, b);
    a = lo;
}

// Batcher odd-even mergesort, n=16, 63 comparators, fully unrolled.
__device__ __forceinline__ void sort16(float* s) {
#pragma unroll
    for (int p = 1; p < NS; p <<= 1) {
#pragma unroll
        for (int k = p; k >= 1; k >>= 1) {
#pragma unroll
            for (int j = k % p; j <= NS - 1 - k; j += 2 * k) {
#pragma unroll
                for (int i = 0; i < k; i++) {
                    if (i <= NS - j - k - 1) {
                        if ((i + j) / (2 * p) == (i + j + k) / (2 * p))
                            ce(s[i + j], s[i + j + k]);
                    }
                }
            }
        }
    }
}

// per-pixel CRPS numerator pieces from a sorted array
__device__ __forceinline__ float crps_sorted(const float* s, float y) {
    // term1 (order-invariant)
    float t1a = 0.0f, t1b = 0.0f;
#pragma unroll
    for (int i = 0; i < NS; i += 2) {
        t1a += fabsf(s[i]     - y);
        t1b += fabsf(s[i + 1] - y);
    }
    // term2 = sum_k (2k-15) s_(k) = sum_{m=0}^{7} (15-2m)(s[15-m] - s[m])
    float t2a = 0.0f, t2b = 0.0f;
#pragma unroll
    for (int m = 0; m < 8; m += 2) {
        t2a = fmaf((float)(15 - 2 * m),       s[15 - m]     - s[m],     t2a);
        t2b = fmaf((float)(15 - 2 * (m + 1)), s[15 - m - 1] - s[m + 1], t2b);
    }
    return (t1a + t1b) * (1.0f / NS) - (t2a + t2b) * (1.0f / (NS * NS));
}

__global__ __launch_bounds__(THREADS) void crps_fused_kernel(
    const float* __restrict__ samples,
    const float* __restrict__ target,
    float* __restrict__ out)
{
    const int tid = threadIdx.x;
    const int v   = blockIdx.x * THREADS + tid;     // float2 group (2 pixels)

    // ---- 17 x LDG.64 coalesced, unpack to two scalar pixel arrays ----
    float s0[NS], s1[NS];
#pragma unroll
    for (int i = 0; i < NS; i++) {
        const float2 p = reinterpret_cast<const float2*>(samples + (size_t)i * NPIX)[v];
        s0[i] = p.x;
        s1[i] = p.y;
    }
    const float2 y = reinterpret_cast<const float2*>(target)[v];

    // ---- sort both pixels' ensembles (independent -> ILP across the two) ----
    sort16(s0);
    sort16(s1);

    float val = crps_sorted(s0, y.x) + crps_sorted(s1, y.y);

    // ---- block reduction (8 warps) ----
    __shared__ float warp_sum[THREADS / 32];
    float w = val;
#pragma unroll
    for (int off = 16; off > 0; off >>= 1)
        w += __shfl_down_sync(0xFFFFFFFFu, w, off);
    if ((tid & 31) == 0) warp_sum[tid >> 5] = w;
    __syncthreads();

    __shared__ bool is_last;
    if (tid == 0) {
        float b = 0.0f;
#pragma unroll
        for (int k = 0; k < THREADS / 32; k++) b += warp_sum[k];
        g_partial[blockIdx.x] = b;
        __threadfence();
        unsigned int ticket = atomicAdd(&g_done, 1u);
        is_last = (ticket == BLOCKS - 1);
    }
    __syncthreads();

    // ---- last block folds the 512 partials ----
    if (is_last) {
        float acc = 0.0f;
#pragma unroll
        for (int k = 0; k < BLOCKS / THREADS; k++)
            acc += g_partial[tid + k * THREADS];
#pragma unroll
        for (int off = 16; off > 0; off >>= 1)
            acc += __shfl_down_sync(0xFFFFFFFFu, acc, off);
        if ((tid & 31) == 0) warp_sum[tid >> 5] = acc;
        __syncthreads();
        if (tid == 0) {
            float total = 0.0f;
#pragma unroll
            for (int k = 0; k < THREADS / 32; k++) total += warp_sum[k];
            out[0] = total * (1.0f / NPIX);
            g_done = 0;                  // reset for next graph replay
        }
    }
}

extern "C" void kernel_launch(void* const* d_in, const int* in_sizes, int n_in,
                              void* d_out, int out_size)
{
    const float* samples = (const float*)d_in[0];
    const float* target  = (const float*)d_in[1];
    crps_fused_kernel<<<BLOCKS, THREADS>>>(samples, target, (float*)d_out);
}